// round 4
// baseline (speedup 1.0000x reference)
#include <cuda_runtime.h>
#include <cstdint>

// Problem constants
#define KS    5
#define NTAP  25
#define OH    508
#define OW    508
#define IH    512
#define IW    512
#define CI    3
#define BATCH 8

#define PLANE  (OH * OW)        // 258064 floats, %4 == 0
#define PLANE4 (PLANE / 4)
#define WTOT   6193536          // 8*3*508*508

// Tile config
#define TW4   32                // float4 columns per tile (x)
#define TWPX  (TW4 * 4)         // 128 pixels wide
#define TH    8                 // rows per tile
#define SW    (TWPX + 4)        // 132 floats per smem row
#define SROWS (TH + 4)          // 12 rows
#define NTHR  (TW4 * TH)        // 256

// Dynamic SMEM layout: tensor tile | 2-deep tap-row ring
#define ST_BYTES   (CI * SROWS * SW * 4)     // 19008
#define SK_OFF     ST_BYTES                  // 16B aligned (19008 % 16 == 0)
#define SK_BYTES   (2 * KS * NTHR * 16)      // 40960
#define SMEM_BYTES (SK_OFF + SK_BYTES)       // 59968

__device__ __forceinline__ void cp16(uint32_t dst_smem, const void* src) {
    asm volatile("cp.async.cg.shared.global [%0], [%1], 16;\n"
                 :: "r"(dst_smem), "l"(src));
}
__device__ __forceinline__ void cp_commit() {
    asm volatile("cp.async.commit_group;\n" ::: "memory");
}
template <int N>
__device__ __forceinline__ void cp_wait() {
    asm volatile("cp.async.wait_group %0;\n" :: "n"(N) : "memory");
}

__global__ __launch_bounds__(NTHR, 3)
void apply_kernels_k(const float* __restrict__ kern,   // [8][25][508][508]
                     const float* __restrict__ tens,   // [8][3][512][512]
                     float* __restrict__ out)          // weighted ++ kernel_sum
{
    extern __shared__ char smem_raw[];
    float  (*s_t)[SROWS][SW] = reinterpret_cast<float(*)[SROWS][SW]>(smem_raw);
    float4* s_k              = reinterpret_cast<float4*>(smem_raw + SK_OFF);

    const int b  = blockIdx.z;
    const int i0 = blockIdx.y * TH;
    const int j0 = blockIdx.x * TWPX;

    const int tx  = threadIdx.x;
    const int ty  = threadIdx.y;
    const int tid = ty * TW4 + tx;
    // clamp instead of early-return: out-of-range threads duplicate valid work
    const int i  = min(i0 + ty, OH - 1);
    const int j  = min(j0 + tx * 4, OW - 4);

    const float4* kp = reinterpret_cast<const float4*>(
        kern + ((size_t)b * NTAP) * PLANE + (size_t)i * OW + j);

    const uint32_t skbase = (uint32_t)__cvta_generic_to_shared(s_k);

    // ---- stage tap row 0 via cp.async (no registers consumed) ----
    #pragma unroll
    for (int t = 0; t < KS; ++t)
        cp16(skbase + (uint32_t)((0 * KS + t) * NTHR + tid) * 16u, kp + t * PLANE4);
    cp_commit();

    // ---- cooperative tensor tile load (3 ch, 12 rows, 132 cols) ----
    {
        const int NV4 = CI * SROWS * (SW / 4);   // 1188 float4 slots
        #pragma unroll 1
        for (int idx = tid; idx < NV4; idx += NTHR) {
            const int c    = idx / (SROWS * (SW / 4));
            const int rem  = idx % (SROWS * (SW / 4));
            const int r    = rem / (SW / 4);
            const int q4   = rem % (SW / 4);
            const int grow = i0 + r;
            const int gcol = j0 + q4 * 4;
            float4 v = make_float4(0.f, 0.f, 0.f, 0.f);
            if (grow < IH && gcol < IW) {
                v = *reinterpret_cast<const float4*>(
                        &tens[(((size_t)b * CI + c) * IH + grow) * IW + gcol]);
            }
            *reinterpret_cast<float4*>(&s_t[c][r][q4 * 4]) = v;
        }
    }
    __syncthreads();

    const int li = i - i0;
    const int lj = j - j0;

    float acc0[4] = {0.f, 0.f, 0.f, 0.f};
    float acc1[4] = {0.f, 0.f, 0.f, 0.f};
    float acc2[4] = {0.f, 0.f, 0.f, 0.f};
    float ssum[4] = {0.f, 0.f, 0.f, 0.f};

    #pragma unroll
    for (int di = 0; di < KS; ++di) {
        // ---- stage next tap row, then wait until current row has landed ----
        if (di < KS - 1) {
            const uint32_t buf = (uint32_t)((di + 1) & 1) * (KS * NTHR);
            #pragma unroll
            for (int t = 0; t < KS; ++t)
                cp16(skbase + (buf + (uint32_t)(t * NTHR + tid)) * 16u,
                     kp + ((di + 1) * KS + t) * PLANE4);
            cp_commit();
            cp_wait<1>();     // current row complete, next row in flight
        } else {
            cp_wait<0>();
        }

        // ---- register-cache the 8 tensor floats per channel for this row ----
        float r0[8], r1[8], r2[8];
        {
            float4 a, bb;
            a  = *reinterpret_cast<const float4*>(&s_t[0][li + di][lj]);
            bb = *reinterpret_cast<const float4*>(&s_t[0][li + di][lj + 4]);
            r0[0]=a.x; r0[1]=a.y; r0[2]=a.z; r0[3]=a.w;
            r0[4]=bb.x; r0[5]=bb.y; r0[6]=bb.z; r0[7]=bb.w;
            a  = *reinterpret_cast<const float4*>(&s_t[1][li + di][lj]);
            bb = *reinterpret_cast<const float4*>(&s_t[1][li + di][lj + 4]);
            r1[0]=a.x; r1[1]=a.y; r1[2]=a.z; r1[3]=a.w;
            r1[4]=bb.x; r1[5]=bb.y; r1[6]=bb.z; r1[7]=bb.w;
            a  = *reinterpret_cast<const float4*>(&s_t[2][li + di][lj]);
            bb = *reinterpret_cast<const float4*>(&s_t[2][li + di][lj + 4]);
            r2[0]=a.x; r2[1]=a.y; r2[2]=a.z; r2[3]=a.w;
            r2[4]=bb.x; r2[5]=bb.y; r2[6]=bb.z; r2[7]=bb.w;
        }

        // ---- consume the staged tap row from SMEM (own slots, no conflicts) ----
        const int buf = (di & 1) * (KS * NTHR);
        #pragma unroll
        for (int dj = 0; dj < KS; ++dj) {
            const float4 k4 = s_k[buf + dj * NTHR + tid];
            const float kv[4] = {k4.x, k4.y, k4.z, k4.w};
            #pragma unroll
            for (int l = 0; l < 4; ++l) {
                const float s = kv[l];
                ssum[l] += s;
                acc0[l] = fmaf(s, r0[l + dj], acc0[l]);
                acc1[l] = fmaf(s, r1[l + dj], acc1[l]);
                acc2[l] = fmaf(s, r2[l + dj], acc2[l]);
            }
        }
    }

    // ---- stores: weighted (3 channels) then kernel_sum ----
    const size_t pix = (size_t)i * OW + j;
    *reinterpret_cast<float4*>(&out[(((size_t)b * CI + 0) * (size_t)PLANE) + pix]) =
        make_float4(acc0[0], acc0[1], acc0[2], acc0[3]);
    *reinterpret_cast<float4*>(&out[(((size_t)b * CI + 1) * (size_t)PLANE) + pix]) =
        make_float4(acc1[0], acc1[1], acc1[2], acc1[3]);
    *reinterpret_cast<float4*>(&out[(((size_t)b * CI + 2) * (size_t)PLANE) + pix]) =
        make_float4(acc2[0], acc2[1], acc2[2], acc2[3]);
    *reinterpret_cast<float4*>(&out[WTOT + (size_t)b * (size_t)PLANE + pix]) =
        make_float4(ssum[0], ssum[1], ssum[2], ssum[3]);
}

extern "C" void kernel_launch(void* const* d_in, const int* in_sizes, int n_in,
                              void* d_out, int out_size)
{
    const float* kern = (const float*)d_in[0];   // (8, 25, 508, 508)
    const float* tens = (const float*)d_in[1];   // (8, 3, 512, 512)
    float* out = (float*)d_out;

    // raise dynamic smem limit (host-side attribute set; deterministic, not an alloc)
    cudaFuncSetAttribute(apply_kernels_k,
                         cudaFuncAttributeMaxDynamicSharedMemorySize, SMEM_BYTES);

    dim3 block(TW4, TH, 1);                       // 256 threads
    dim3 grid((OW / 4 + TW4 - 1) / TW4,           // 4
              (OH + TH - 1) / TH,                 // 64
              BATCH);                             // 8
    apply_kernels_k<<<grid, block, SMEM_BYTES>>>(kern, tens, out);
}